// round 8
// baseline (speedup 1.0000x reference)
#include <cuda_runtime.h>
#include <cuda_fp16.h>
#include <mma.h>

using namespace nvcuda;

#define N_NODES   100000
#define N_HEDGES  25000
#define CH        128
#define STRIDE_E  192     // max supported hyperedge degree (mean 64)
#define STRIDE_V  64      // max supported node degree (mean 16)

#define GEMM_ROWS 64
#define M_PAD     ((N_HEDGES + GEMM_ROWS - 1) / GEMM_ROWS * GEMM_ROWS)  // 25024

#define SB_LD     136     // padded half-stride (17 x 16B) -> conflict-free LDSM
#define GEMM_SMEM (GEMM_ROWS * SB_LD * 2 + CH * SB_LD * 2)  // 17408 + 34816 = 52224

// ---------------------------------------------------------------------------
// Static device scratch (no allocation in kernel_launch; zero-init at load)
// ---------------------------------------------------------------------------
__device__ __half g_Xh[N_NODES * CH];        // fp16 copy of X              25.6 MB
__device__ __half g_XeSumH[M_PAD * CH];      // segsum1(X) fp16 (tail = 0)   6.4 MB
__device__ __half g_Xeh[N_HEDGES * CH];      // (XeSum@W)*degE*Wbuf fp16     6.4 MB

__device__ int g_cntE[N_HEDGES];             // zero-invariant between calls
__device__ int g_cntV[N_NODES];              // (gathers reset after reading)
__device__ int g_adjE[N_HEDGES * STRIDE_E];
__device__ int g_adjV[N_NODES  * STRIDE_V];

// ---------------------------------------------------------------------------
// Fused bucket-fill + X->fp16 convert. Interleaved roles by block parity so
// the DRAM-streaming f2h overlaps the L2-atomic-bound fill.
// ---------------------------------------------------------------------------
__global__ void fill_f2h_kernel(const int* __restrict__ src,
                                const int* __restrict__ dst,
                                int* __restrict__ cntV, int* __restrict__ cntE,
                                int* __restrict__ adjV, int* __restrict__ adjE,
                                int nnz, int fillB,
                                const float* __restrict__ Xf,
                                __half* __restrict__ Xh, int n8, int f2hB) {
    int bid = blockIdx.x;
    int nInter = 2 * min(fillB, f2hB);
    int role, idx;                      // role 0 = fill, 1 = f2h
    if (bid < nInter) { role = bid & 1; idx = bid >> 1; }
    else { idx = bid - nInter / 2; role = (fillB > f2hB) ? 0 : 1; }

    if (role == 0) {
        int i = idx * blockDim.x + threadIdx.x;
        if (i >= nnz) return;
        int s = __ldg(src + i);
        int d = __ldg(dst + i);
        int pe = atomicAdd(cntE + d, 1);
        if (pe < STRIDE_E) adjE[d * STRIDE_E + pe] = s;
        int pv = atomicAdd(cntV + s, 1);
        if (pv < STRIDE_V) adjV[s * STRIDE_V + pv] = d;
    } else {
        int i = idx * blockDim.x + threadIdx.x;
        if (i >= n8) return;
        float4 a = __ldg(reinterpret_cast<const float4*>(Xf) + 2 * i);
        float4 b = __ldg(reinterpret_cast<const float4*>(Xf) + 2 * i + 1);
        __half2 h0 = __floats2half2_rn(a.x, a.y);
        __half2 h1 = __floats2half2_rn(a.z, a.w);
        __half2 h2 = __floats2half2_rn(b.x, b.y);
        __half2 h3 = __floats2half2_rn(b.z, b.w);
        uint4 u;
        u.x = *reinterpret_cast<unsigned*>(&h0);
        u.y = *reinterpret_cast<unsigned*>(&h1);
        u.z = *reinterpret_cast<unsigned*>(&h2);
        u.w = *reinterpret_cast<unsigned*>(&h3);
        reinterpret_cast<uint4*>(Xh)[i] = u;
    }
}

// ---------------------------------------------------------------------------
// Per-segment gather-sum, fp16 table. 16 lanes x 8 channels, 2 edge streams.
// 4-edge groups: pairwise HADD2 in fp16, then cvt + fp32 accumulate
// (cuts fma-pipe ops ~40%). Resets cnt[seg] = 0 after reading (invariant).
// ---------------------------------------------------------------------------
template <typename OutT, bool STREAM>
__global__ void gather_sum_kernel(const __half* __restrict__ feat,
                                  const int* __restrict__ adj,
                                  int* __restrict__ cnt,
                                  int stride, int maxcnt,
                                  const float* __restrict__ rowscale,
                                  OutT* __restrict__ out,
                                  int nseg) {
    int seg  = (blockIdx.x * blockDim.x + threadIdx.x) >> 5;
    int lane = threadIdx.x & 31;
    if (seg >= nseg) return;

    const int parity = lane >> 4;
    const int sub    = lane & 15;
    const int start  = seg * stride;
    int n = __ldg(cnt + seg);
    if (lane == 0) cnt[seg] = 0;            // restore zero for next call
    if (n > maxcnt) n = maxcnt;

    const uint4* F = reinterpret_cast<const uint4*>(feat);

    float a0=0.f,a1=0.f,a2=0.f,a3=0.f,a4=0.f,a5=0.f,a6=0.f,a7=0.f;

    int j = parity;
    for (; j + 6 < n; j += 8) {             // 4 edges per stream per iter
        int id[4];
        #pragma unroll
        for (int u = 0; u < 4; u++) id[u] = __ldg(adj + start + j + 2 * u);
        uint4 r[4];
        #pragma unroll
        for (int u = 0; u < 4; u++) r[u] = __ldg(F + (size_t)id[u] * 16 + sub);

        const __half2* h0 = reinterpret_cast<const __half2*>(&r[0]);
        const __half2* h1 = reinterpret_cast<const __half2*>(&r[1]);
        const __half2* h2 = reinterpret_cast<const __half2*>(&r[2]);
        const __half2* h3 = reinterpret_cast<const __half2*>(&r[3]);
        #pragma unroll
        for (int c = 0; c < 4; c++) {
            __half2 s01 = __hadd2(h0[c], h1[c]);   // one fp16 add level
            __half2 s23 = __hadd2(h2[c], h3[c]);
            float2 f0 = __half22float2(s01);
            float2 f1 = __half22float2(s23);
            switch (c) {
                case 0: a0 += f0.x + f1.x; a1 += f0.y + f1.y; break;
                case 1: a2 += f0.x + f1.x; a3 += f0.y + f1.y; break;
                case 2: a4 += f0.x + f1.x; a5 += f0.y + f1.y; break;
                case 3: a6 += f0.x + f1.x; a7 += f0.y + f1.y; break;
            }
        }
    }
    for (; j < n; j += 2) {
        int id = __ldg(adj + start + j);
        uint4 r = __ldg(F + (size_t)id * 16 + sub);
        float2 f;
        f = __half22float2(*reinterpret_cast<__half2*>(&r.x)); a0 += f.x; a1 += f.y;
        f = __half22float2(*reinterpret_cast<__half2*>(&r.y)); a2 += f.x; a3 += f.y;
        f = __half22float2(*reinterpret_cast<__half2*>(&r.z)); a4 += f.x; a5 += f.y;
        f = __half22float2(*reinterpret_cast<__half2*>(&r.w)); a6 += f.x; a7 += f.y;
    }

    a0 += __shfl_down_sync(0xffffffffu, a0, 16);
    a1 += __shfl_down_sync(0xffffffffu, a1, 16);
    a2 += __shfl_down_sync(0xffffffffu, a2, 16);
    a3 += __shfl_down_sync(0xffffffffu, a3, 16);
    a4 += __shfl_down_sync(0xffffffffu, a4, 16);
    a5 += __shfl_down_sync(0xffffffffu, a5, 16);
    a6 += __shfl_down_sync(0xffffffffu, a6, 16);
    a7 += __shfl_down_sync(0xffffffffu, a7, 16);

    if (parity == 0) {
        float s = rowscale ? __ldg(rowscale + seg) : 1.0f;
        a0*=s; a1*=s; a2*=s; a3*=s; a4*=s; a5*=s; a6*=s; a7*=s;
        if (sizeof(OutT) == 2) {
            __half2 h0 = __floats2half2_rn(a0, a1);
            __half2 h1 = __floats2half2_rn(a2, a3);
            __half2 h2 = __floats2half2_rn(a4, a5);
            __half2 h3 = __floats2half2_rn(a6, a7);
            uint4 u;
            u.x = *reinterpret_cast<unsigned*>(&h0);
            u.y = *reinterpret_cast<unsigned*>(&h1);
            u.z = *reinterpret_cast<unsigned*>(&h2);
            u.w = *reinterpret_cast<unsigned*>(&h3);
            reinterpret_cast<uint4*>(reinterpret_cast<__half*>(out) + (size_t)seg * CH)[sub] = u;
        } else {
            float* p = reinterpret_cast<float*>(out) + (size_t)seg * CH + sub * 8;
            if (STREAM) {
                asm volatile("st.global.cs.v4.f32 [%0], {%1, %2, %3, %4};"
                             :: "l"(p), "f"(a0), "f"(a1), "f"(a2), "f"(a3) : "memory");
                asm volatile("st.global.cs.v4.f32 [%0], {%1, %2, %3, %4};"
                             :: "l"(p + 4), "f"(a4), "f"(a5), "f"(a6), "f"(a7) : "memory");
            } else {
                reinterpret_cast<float4*>(p)[0] = make_float4(a0, a1, a2, a3);
                reinterpret_cast<float4*>(p)[1] = make_float4(a4, a5, a6, a7);
            }
        }
    }
}

// ---------------------------------------------------------------------------
// HMMA GEMM + per-row scale, fp16 in/out, fp32 accumulate.
// A staged through smem (coalesced), both tiles padded to SB_LD=136 halves
// (conflict-free ldmatrix). Dynamic smem 52224 B. Smem reused for C tiles.
// ---------------------------------------------------------------------------
__global__ void gemm_hmma_kernel(const __half* __restrict__ A,
                                 const float*  __restrict__ Wl,
                                 const float*  __restrict__ degE,
                                 const float*  __restrict__ Wbuf,
                                 __half*       __restrict__ outh,
                                 int M) {
    extern __shared__ __align__(16) char smem[];
    __half* sA = reinterpret_cast<__half*>(smem);                       // 64 x 136
    __half* sB = reinterpret_cast<__half*>(smem) + GEMM_ROWS * SB_LD;   // 128 x 136

    const int tid  = threadIdx.x;          // 0..127
    const int warp = tid >> 5;
    const int lane = tid & 31;
    const int row0blk = blockIdx.x * GEMM_ROWS;

    // Stage A tile (64 x 128 half), coalesced uint4: 1024 loads / 128 thr = 8
    {
        const uint4* Ag = reinterpret_cast<const uint4*>(A + (size_t)row0blk * CH);
        #pragma unroll
        for (int t = 0; t < 8; t++) {
            int i = tid + t * 128;         // i in [0,1024)
            int r = i >> 4, c = i & 15;    // 16 uint4 per row
            reinterpret_cast<uint4*>(sA + r * SB_LD)[0 + c] =
                __ldg(Ag + r * 16 + c);
        }
    }
    // Stage Wlin as fp16 (128 x 128), padded
    for (int i = tid; i < CH * CH / 2; i += 128) {
        int r = i / (CH / 2), c = i % (CH / 2);
        float2 w = __ldg(reinterpret_cast<const float2*>(Wl) + i);
        reinterpret_cast<__half2*>(sB + r * SB_LD)[c] = __floats2half2_rn(w.x, w.y);
    }
    __syncthreads();

    wmma::fragment<wmma::accumulator, 16, 16, 16, float> c[8];
    #pragma unroll
    for (int nf = 0; nf < 8; nf++) wmma::fill_fragment(c[nf], 0.0f);

    #pragma unroll
    for (int k = 0; k < 8; k++) {
        wmma::fragment<wmma::matrix_a, 16, 16, 16, __half, wmma::row_major> af;
        wmma::load_matrix_sync(af, sA + warp * 16 * SB_LD + k * 16, SB_LD);
        #pragma unroll
        for (int nf = 0; nf < 8; nf++) {
            wmma::fragment<wmma::matrix_b, 16, 16, 16, __half, wmma::row_major> bf;
            wmma::load_matrix_sync(bf, sB + k * 16 * SB_LD + nf * 16, SB_LD);
            wmma::mma_sync(c[nf], af, bf, c[nf]);
        }
    }

    __syncthreads();   // smem reuse: fp32 C tiles (64 x 128 = 32 KB)
    float* sC = reinterpret_cast<float*>(smem) + warp * 16 * CH;
    #pragma unroll
    for (int nf = 0; nf < 8; nf++)
        wmma::store_matrix_sync(sC + nf * 16, c[nf], CH, wmma::mem_row_major);
    __syncwarp();

    const int row0 = row0blk + warp * 16;
    const int c0 = (lane & 7) * 16;
    for (int r = lane >> 3; r < 16; r += 4) {
        int row = row0 + r;
        if (row >= M) break;
        float s = __ldg(degE + row) * __ldg(Wbuf + row);
        __half2* dst = reinterpret_cast<__half2*>(outh + (size_t)row * CH);
        #pragma unroll
        for (int cc = 0; cc < 16; cc += 2) {
            float x = sC[r * CH + c0 + cc]     * s;
            float y = sC[r * CH + c0 + cc + 1] * s;
            dst[(c0 + cc) >> 1] = __floats2half2_rn(x, y);
        }
    }
}

// ---------------------------------------------------------------------------
// Launch: fill+f2h(1), gather1(2), gemm(3), gather2(4 <- ncu capture slot)
// ---------------------------------------------------------------------------
extern "C" void kernel_launch(void* const* d_in, const int* in_sizes, int n_in,
                              void* d_out, int out_size) {
    const float* X     = (const float*)d_in[0];
    const float* Wlin  = (const float*)d_in[1];
    const float* degE  = (const float*)d_in[2];
    const float* degV  = (const float*)d_in[3];
    const float* Wbuf  = (const float*)d_in[4];
    const int*   g1src = (const int*)d_in[5];
    const int*   g1dst = (const int*)d_in[6];
    const int    nnz   = in_sizes[5];

    float* out = (float*)d_out;

    __half *Xh, *XeSumH, *Xeh;
    int *cntE, *cntV, *adjE, *adjV;
    cudaGetSymbolAddress((void**)&Xh,     g_Xh);
    cudaGetSymbolAddress((void**)&XeSumH, g_XeSumH);
    cudaGetSymbolAddress((void**)&Xeh,    g_Xeh);
    cudaGetSymbolAddress((void**)&cntE,   g_cntE);
    cudaGetSymbolAddress((void**)&cntV,   g_cntV);
    cudaGetSymbolAddress((void**)&adjE,   g_adjE);
    cudaGetSymbolAddress((void**)&adjV,   g_adjV);

    static bool attrDone = false;
    if (!attrDone) {
        cudaFuncSetAttribute(gemm_hmma_kernel,
                             cudaFuncAttributeMaxDynamicSharedMemorySize, GEMM_SMEM);
        attrDone = true;
    }

    // 1) fused fill + f2h (counters pre-zeroed: static init / gather reset)
    {
        int n8    = N_NODES * CH / 8;
        int fillB = (nnz + 255) / 256;
        int f2hB  = (n8 + 255) / 256;
        fill_f2h_kernel<<<fillB + f2hB, 256>>>(g1src, g1dst, cntV, cntE,
                                               adjV, adjE, nnz, fillB,
                                               X, Xh, n8, f2hB);
    }
    // 2) Stage 1: node -> hyperedge gather, fp16 sums out (resets cntE)
    {
        long long threads = (long long)N_HEDGES * 32;
        gather_sum_kernel<__half, false><<<(int)((threads + 255) / 256), 256>>>(
            Xh, adjE, cntE, STRIDE_E, STRIDE_E, nullptr, XeSumH, N_HEDGES);
    }
    // 3) HMMA projection + degE * W scaling, fp16 output table
    gemm_hmma_kernel<<<M_PAD / GEMM_ROWS, 128, GEMM_SMEM>>>(
        XeSumH, Wlin, degE, Wbuf, Xeh, N_HEDGES);
    // 4) Stage 2: hyperedge -> node gather, fused *degV, streaming (resets cntV)
    {
        long long threads = (long long)N_NODES * 32;
        gather_sum_kernel<float, true><<<(int)((threads + 255) / 256), 256>>>(
            Xeh, adjV, cntV, STRIDE_V, STRIDE_V, degV, out, N_NODES);
    }
}

// round 9
// speedup vs baseline: 2.3297x; 2.3297x over previous
#include <cuda_runtime.h>
#include <cuda_fp16.h>
#include <mma.h>

using namespace nvcuda;

#define N_NODES   100000
#define N_HEDGES  25000
#define CH        128
#define STRIDE_E  192     // max supported hyperedge degree (mean 64)
#define STRIDE_V  64      // max supported node degree (mean 16)

#define GEMM_ROWS 64
#define M_PAD     ((N_HEDGES + GEMM_ROWS - 1) / GEMM_ROWS * GEMM_ROWS)  // 25024

// ---------------------------------------------------------------------------
// Static device scratch (zero-initialized at module load; never allocated).
// Each gathered feature table has ONE extra row that is never written and
// therefore stays all-zero: out-of-range gather slots read it harmlessly.
// ---------------------------------------------------------------------------
__device__ __half g_Xh[(N_NODES + 1) * CH];   // fp16 X + zero row       25.6 MB
__device__ __half g_XeSumH[M_PAD * CH];       // segsum1(X) fp16 (tail 0) 6.4 MB
__device__ __half g_Xeh[(N_HEDGES + 1) * CH]; // scaled proj + zero row   6.4 MB

__device__ int g_cntE[N_HEDGES];
__device__ int g_cntV[N_NODES];
__device__ int g_adjE[N_HEDGES * STRIDE_E];
__device__ int g_adjV[N_NODES  * STRIDE_V];

// ---------------------------------------------------------------------------
// Fused: zero both count arrays (blocks [0, zeroB)) + X -> fp16 (the rest).
// Both are pure streaming writes to disjoint buffers; runs before fill.
// ---------------------------------------------------------------------------
__global__ void zero_f2h_kernel(int* __restrict__ cntV, int nV,
                                int* __restrict__ cntE, int nE, int zeroB,
                                const float* __restrict__ Xf,
                                __half* __restrict__ Xh, int n8) {
    if ((int)blockIdx.x < zeroB) {
        int i = blockIdx.x * blockDim.x + threadIdx.x;
        if (i < nV) cntV[i] = 0;
        if (i < nE) cntE[i] = 0;
    } else {
        int i = (blockIdx.x - zeroB) * blockDim.x + threadIdx.x;
        if (i >= n8) return;
        float4 a = __ldg(reinterpret_cast<const float4*>(Xf) + 2 * i);
        float4 b = __ldg(reinterpret_cast<const float4*>(Xf) + 2 * i + 1);
        __half2 h0 = __floats2half2_rn(a.x, a.y);
        __half2 h1 = __floats2half2_rn(a.z, a.w);
        __half2 h2 = __floats2half2_rn(b.x, b.y);
        __half2 h3 = __floats2half2_rn(b.z, b.w);
        uint4 u;
        u.x = *reinterpret_cast<unsigned*>(&h0);
        u.y = *reinterpret_cast<unsigned*>(&h1);
        u.z = *reinterpret_cast<unsigned*>(&h2);
        u.w = *reinterpret_cast<unsigned*>(&h3);
        reinterpret_cast<uint4*>(Xh)[i] = u;
    }
}

// ---------------------------------------------------------------------------
// Direct fixed-stride bucket fill (no hist, no scan)
// ---------------------------------------------------------------------------
__global__ void fill_kernel(const int* __restrict__ src,
                            const int* __restrict__ dst,
                            int* __restrict__ cntV, int* __restrict__ cntE,
                            int* __restrict__ adjV, int* __restrict__ adjE,
                            int nnz) {
    int i = blockIdx.x * blockDim.x + threadIdx.x;
    if (i >= nnz) return;
    int s = __ldg(src + i);
    int d = __ldg(dst + i);
    int pe = atomicAdd(cntE + d, 1);
    if (pe < STRIDE_E) adjE[d * STRIDE_E + pe] = s;
    int pv = atomicAdd(cntV + s, 1);
    if (pv < STRIDE_V) adjV[s * STRIDE_V + pv] = d;
}

// ---------------------------------------------------------------------------
// Per-segment gather-sum, fp16 table, fp32 accumulate. Branch-free:
// 16 lanes x 8 channels, 2 edge streams; 8 slots per stream per iteration,
// out-of-range slots redirected to the all-zero pad row (exact +0).
// ---------------------------------------------------------------------------
template <typename OutT, bool STREAM>
__global__ void gather_sum_kernel(const __half* __restrict__ feat,
                                  const int* __restrict__ adj,
                                  const int* __restrict__ cnt,
                                  int stride, int maxcnt, int zeroRow,
                                  const float* __restrict__ rowscale,
                                  OutT* __restrict__ out,
                                  int nseg) {
    int seg  = (blockIdx.x * blockDim.x + threadIdx.x) >> 5;
    int lane = threadIdx.x & 31;
    if (seg >= nseg) return;

    const int parity = lane >> 4;   // edge stream 0/1 (even/odd slots)
    const int sub    = lane & 15;   // channel group [sub*8, sub*8+8)
    const int start  = seg * stride;
    int n = __ldg(cnt + seg);
    if (n > maxcnt) n = maxcnt;

    const uint4* F = reinterpret_cast<const uint4*>(feat);

    float a0=0.f,a1=0.f,a2=0.f,a3=0.f,a4=0.f,a5=0.f,a6=0.f,a7=0.f;

    for (int j = parity; j < n; j += 16) {     // 8 slots per stream per iter
        int id[8];
        #pragma unroll
        for (int u = 0; u < 8; u++) {
            int jj = j + 2 * u;
            id[u] = (jj < n) ? __ldg(adj + start + jj) : zeroRow;
        }
        uint4 r[8];
        #pragma unroll
        for (int u = 0; u < 8; u++)
            r[u] = __ldg(F + (size_t)id[u] * 16 + sub);
        #pragma unroll
        for (int u = 0; u < 8; u++) {
            float2 f;
            f = __half22float2(*reinterpret_cast<__half2*>(&r[u].x)); a0 += f.x; a1 += f.y;
            f = __half22float2(*reinterpret_cast<__half2*>(&r[u].y)); a2 += f.x; a3 += f.y;
            f = __half22float2(*reinterpret_cast<__half2*>(&r[u].z)); a4 += f.x; a5 += f.y;
            f = __half22float2(*reinterpret_cast<__half2*>(&r[u].w)); a6 += f.x; a7 += f.y;
        }
    }

    // combine the two edge streams: lane L (<16) += lane L+16
    a0 += __shfl_down_sync(0xffffffffu, a0, 16);
    a1 += __shfl_down_sync(0xffffffffu, a1, 16);
    a2 += __shfl_down_sync(0xffffffffu, a2, 16);
    a3 += __shfl_down_sync(0xffffffffu, a3, 16);
    a4 += __shfl_down_sync(0xffffffffu, a4, 16);
    a5 += __shfl_down_sync(0xffffffffu, a5, 16);
    a6 += __shfl_down_sync(0xffffffffu, a6, 16);
    a7 += __shfl_down_sync(0xffffffffu, a7, 16);

    if (parity == 0) {
        float s = rowscale ? __ldg(rowscale + seg) : 1.0f;
        a0*=s; a1*=s; a2*=s; a3*=s; a4*=s; a5*=s; a6*=s; a7*=s;
        if (sizeof(OutT) == 2) {     // fp16 output: one uint4 store
            __half2 h0 = __floats2half2_rn(a0, a1);
            __half2 h1 = __floats2half2_rn(a2, a3);
            __half2 h2 = __floats2half2_rn(a4, a5);
            __half2 h3 = __floats2half2_rn(a6, a7);
            uint4 u;
            u.x = *reinterpret_cast<unsigned*>(&h0);
            u.y = *reinterpret_cast<unsigned*>(&h1);
            u.z = *reinterpret_cast<unsigned*>(&h2);
            u.w = *reinterpret_cast<unsigned*>(&h3);
            reinterpret_cast<uint4*>(reinterpret_cast<__half*>(out) + (size_t)seg * CH)[sub] = u;
        } else {                     // fp32 output: two float4 stores
            float* p = reinterpret_cast<float*>(out) + (size_t)seg * CH + sub * 8;
            if (STREAM) {
                asm volatile("st.global.cs.v4.f32 [%0], {%1, %2, %3, %4};"
                             :: "l"(p), "f"(a0), "f"(a1), "f"(a2), "f"(a3) : "memory");
                asm volatile("st.global.cs.v4.f32 [%0], {%1, %2, %3, %4};"
                             :: "l"(p + 4), "f"(a4), "f"(a5), "f"(a6), "f"(a7) : "memory");
            } else {
                reinterpret_cast<float4*>(p)[0] = make_float4(a0, a1, a2, a3);
                reinterpret_cast<float4*>(p)[1] = make_float4(a4, a5, a6, a7);
            }
        }
    }
}

// ---------------------------------------------------------------------------
// HMMA GEMM + per-row scale (round-6 proven version): fp16 in/out, fp32 acc.
// Block = 4 warps = 64 rows. Static 32KB smem holds Wl(half) during K loop,
// reused for fp32 C tiles in the epilogue.
// ---------------------------------------------------------------------------
__global__ void gemm_hmma_kernel(const __half* __restrict__ A,
                                 const float*  __restrict__ Wl,
                                 const float*  __restrict__ degE,
                                 const float*  __restrict__ Wbuf,
                                 __half*       __restrict__ outh,
                                 int M) {
    __shared__ __align__(32) char smem[CH * CH * 2];   // 32 KB

    const int tid  = threadIdx.x;          // 0..127
    const int warp = tid >> 5;
    const int lane = tid & 31;

    __half* sB = reinterpret_cast<__half*>(smem);
    for (int i = tid; i < CH * CH / 2; i += 128) {
        float2 w = __ldg(reinterpret_cast<const float2*>(Wl) + i);
        reinterpret_cast<__half2*>(sB)[i] = __floats2half2_rn(w.x, w.y);
    }
    __syncthreads();

    const int row0 = blockIdx.x * GEMM_ROWS + warp * 16;

    wmma::fragment<wmma::accumulator, 16, 16, 16, float> c[8];
    #pragma unroll
    for (int nf = 0; nf < 8; nf++) wmma::fill_fragment(c[nf], 0.0f);

    const __half* Arow = A + (size_t)row0 * CH;
    #pragma unroll
    for (int k = 0; k < 8; k++) {
        wmma::fragment<wmma::matrix_a, 16, 16, 16, __half, wmma::row_major> af;
        wmma::load_matrix_sync(af, Arow + k * 16, CH);
        #pragma unroll
        for (int nf = 0; nf < 8; nf++) {
            wmma::fragment<wmma::matrix_b, 16, 16, 16, __half, wmma::row_major> bf;
            wmma::load_matrix_sync(bf, sB + k * 16 * CH + nf * 16, CH);
            wmma::mma_sync(c[nf], af, bf, c[nf]);
        }
    }

    __syncthreads();   // reuse smem for C tiles
    float* sC = reinterpret_cast<float*>(smem) + warp * 16 * CH;
    #pragma unroll
    for (int nf = 0; nf < 8; nf++)
        wmma::store_matrix_sync(sC + nf * 16, c[nf], CH, wmma::mem_row_major);
    __syncwarp();

    const int c0 = (lane & 7) * 16;
    for (int r = lane >> 3; r < 16; r += 4) {
        int row = row0 + r;
        if (row >= M) break;
        float s = __ldg(degE + row) * __ldg(Wbuf + row);
        __half2* dst = reinterpret_cast<__half2*>(outh + (size_t)row * CH);
        #pragma unroll
        for (int cc = 0; cc < 16; cc += 2) {
            float x = sC[r * CH + c0 + cc]     * s;
            float y = sC[r * CH + c0 + cc + 1] * s;
            dst[(c0 + cc) >> 1] = __floats2half2_rn(x, y);
        }
    }
}

// ---------------------------------------------------------------------------
// Launch: zero+f2h(1), fill(2), gather1(3), gemm(4 <- ncu slot), gather2(5)
// ---------------------------------------------------------------------------
extern "C" void kernel_launch(void* const* d_in, const int* in_sizes, int n_in,
                              void* d_out, int out_size) {
    const float* X     = (const float*)d_in[0];
    const float* Wlin  = (const float*)d_in[1];
    const float* degE  = (const float*)d_in[2];
    const float* degV  = (const float*)d_in[3];
    const float* Wbuf  = (const float*)d_in[4];
    const int*   g1src = (const int*)d_in[5];
    const int*   g1dst = (const int*)d_in[6];
    const int    nnz   = in_sizes[5];

    float* out = (float*)d_out;

    __half *Xh, *XeSumH, *Xeh;
    int *cntE, *cntV, *adjE, *adjV;
    cudaGetSymbolAddress((void**)&Xh,     g_Xh);
    cudaGetSymbolAddress((void**)&XeSumH, g_XeSumH);
    cudaGetSymbolAddress((void**)&Xeh,    g_Xeh);
    cudaGetSymbolAddress((void**)&cntE,   g_cntE);
    cudaGetSymbolAddress((void**)&cntV,   g_cntV);
    cudaGetSymbolAddress((void**)&adjE,   g_adjE);
    cudaGetSymbolAddress((void**)&adjV,   g_adjV);

    // 1) fused zero counters + X -> fp16
    {
        int n8    = N_NODES * CH / 8;
        int zeroB = (N_NODES + 255) / 256;
        int f2hB  = (n8 + 255) / 256;
        zero_f2h_kernel<<<zeroB + f2hB, 256>>>(cntV, N_NODES, cntE, N_HEDGES,
                                               zeroB, X, Xh, n8);
    }
    // 2) fixed-stride bucket fill
    fill_kernel<<<(nnz + 255) / 256, 256>>>(g1src, g1dst, cntV, cntE, adjV, adjE, nnz);
    // 3) Stage 1: node -> hyperedge gather, fp16 sums out
    {
        long long threads = (long long)N_HEDGES * 32;
        gather_sum_kernel<__half, false><<<(int)((threads + 255) / 256), 256>>>(
            Xh, adjE, cntE, STRIDE_E, STRIDE_E, N_NODES, nullptr, XeSumH, N_HEDGES);
    }
    // 4) HMMA projection + degE * W scaling, fp16 output table
    gemm_hmma_kernel<<<M_PAD / GEMM_ROWS, 128>>>(XeSumH, Wlin, degE, Wbuf, Xeh, N_HEDGES);
    // 5) Stage 2: hyperedge -> node gather, fused *degV, streaming fp32 out
    {
        long long threads = (long long)N_NODES * 32;
        gather_sum_kernel<float, true><<<(int)((threads + 255) / 256), 256>>>(
            Xeh, adjV, cntV, STRIDE_V, STRIDE_V, N_HEDGES, degV, out, N_NODES);
    }
}

// round 13
// speedup vs baseline: 2.7608x; 1.1851x over previous
#include <cuda_runtime.h>
#include <cuda_fp16.h>
#include <mma.h>

using namespace nvcuda;

#define N_NODES   100000
#define N_HEDGES  25000
#define CH        128
#define STRIDE_E  192     // max supported hyperedge degree (mean 64)
#define STRIDE_V  64      // max supported node degree (mean 16)

#define GEMM_ROWS 128                                  // rows per block (8 warps x 16)
#define M_PAD     ((N_HEDGES + GEMM_ROWS - 1) / GEMM_ROWS * GEMM_ROWS)  // 25088

#define SB_LD     136     // padded half stride: 272 B = 17 x 16 B -> conflict-free ldmatrix
#define SC_LD     132     // padded float stride for C tiles
#define GEMM_SMEM (2 * GEMM_ROWS * SB_LD * 2)          // sA + sB = 69632 B

// ---------------------------------------------------------------------------
// Static device scratch (zero-initialized at module load; never allocated).
// g_XeSumH tail rows [25000, 25088) are never written -> stay zero (GEMM pad).
// ---------------------------------------------------------------------------
__device__ __half g_Xh[N_NODES * CH];        // fp16 copy of X              25.6 MB
__device__ __half g_XeSumH[M_PAD * CH];      // segsum1(X) fp16 (tail 0)     6.4 MB
__device__ __half g_Xeh[N_HEDGES * CH];      // (XeSum@W)*degE*Wbuf fp16     6.4 MB

__device__ int g_cntE[N_HEDGES];
__device__ int g_cntV[N_NODES];
__device__ int g_adjE[N_HEDGES * STRIDE_E];
__device__ int g_adjV[N_NODES  * STRIDE_V];

// ---------------------------------------------------------------------------
// Fused: zero both count arrays (blocks [0, zeroB)) + X -> fp16 (the rest).
// ---------------------------------------------------------------------------
__global__ void zero_f2h_kernel(int* __restrict__ cntV, int nV,
                                int* __restrict__ cntE, int nE, int zeroB,
                                const float* __restrict__ Xf,
                                __half* __restrict__ Xh, int n8) {
    if ((int)blockIdx.x < zeroB) {
        int i = blockIdx.x * blockDim.x + threadIdx.x;
        if (i < nV) cntV[i] = 0;
        if (i < nE) cntE[i] = 0;
    } else {
        int i = (blockIdx.x - zeroB) * blockDim.x + threadIdx.x;
        if (i >= n8) return;
        float4 a = __ldg(reinterpret_cast<const float4*>(Xf) + 2 * i);
        float4 b = __ldg(reinterpret_cast<const float4*>(Xf) + 2 * i + 1);
        __half2 h0 = __floats2half2_rn(a.x, a.y);
        __half2 h1 = __floats2half2_rn(a.z, a.w);
        __half2 h2 = __floats2half2_rn(b.x, b.y);
        __half2 h3 = __floats2half2_rn(b.z, b.w);
        uint4 u;
        u.x = *reinterpret_cast<unsigned*>(&h0);
        u.y = *reinterpret_cast<unsigned*>(&h1);
        u.z = *reinterpret_cast<unsigned*>(&h2);
        u.w = *reinterpret_cast<unsigned*>(&h3);
        reinterpret_cast<uint4*>(Xh)[i] = u;
    }
}

// ---------------------------------------------------------------------------
// Direct fixed-stride bucket fill (no hist, no scan)
// ---------------------------------------------------------------------------
__global__ void fill_kernel(const int* __restrict__ src,
                            const int* __restrict__ dst,
                            int* __restrict__ cntV, int* __restrict__ cntE,
                            int* __restrict__ adjV, int* __restrict__ adjE,
                            int nnz) {
    int i = blockIdx.x * blockDim.x + threadIdx.x;
    if (i >= nnz) return;
    int s = __ldg(src + i);
    int d = __ldg(dst + i);
    int pe = atomicAdd(cntE + d, 1);
    if (pe < STRIDE_E) adjE[d * STRIDE_E + pe] = s;
    int pv = atomicAdd(cntV + s, 1);
    if (pv < STRIDE_V) adjV[s * STRIDE_V + pv] = d;
}

// ---------------------------------------------------------------------------
// Per-segment gather-sum (round-6 proven body): fp16 table, fp32 accumulate.
// 16 lanes x 8 channels (uint4 = 8 halves), 2 edge streams, shuffle combine.
// ---------------------------------------------------------------------------
template <typename OutT, bool STREAM>
__global__ void gather_sum_kernel(const __half* __restrict__ feat,
                                  const int* __restrict__ adj,
                                  const int* __restrict__ cnt,
                                  int stride, int maxcnt,
                                  const float* __restrict__ rowscale,
                                  OutT* __restrict__ out,
                                  int nseg) {
    int seg  = (blockIdx.x * blockDim.x + threadIdx.x) >> 5;
    int lane = threadIdx.x & 31;
    if (seg >= nseg) return;

    const int parity = lane >> 4;
    const int sub    = lane & 15;
    const int start  = seg * stride;
    int n = __ldg(cnt + seg);
    if (n > maxcnt) n = maxcnt;

    const uint4* F = reinterpret_cast<const uint4*>(feat);

    float a0=0.f,a1=0.f,a2=0.f,a3=0.f,a4=0.f,a5=0.f,a6=0.f,a7=0.f;

    int j = parity;
    for (; j + 6 < n; j += 8) {
        int id[4];
        #pragma unroll
        for (int u = 0; u < 4; u++) id[u] = __ldg(adj + start + j + 2 * u);
        uint4 r[4];
        #pragma unroll
        for (int u = 0; u < 4; u++) r[u] = __ldg(F + (size_t)id[u] * 16 + sub);
        #pragma unroll
        for (int u = 0; u < 4; u++) {
            float2 f;
            f = __half22float2(*reinterpret_cast<__half2*>(&r[u].x)); a0 += f.x; a1 += f.y;
            f = __half22float2(*reinterpret_cast<__half2*>(&r[u].y)); a2 += f.x; a3 += f.y;
            f = __half22float2(*reinterpret_cast<__half2*>(&r[u].z)); a4 += f.x; a5 += f.y;
            f = __half22float2(*reinterpret_cast<__half2*>(&r[u].w)); a6 += f.x; a7 += f.y;
        }
    }
    for (; j < n; j += 2) {
        int id = __ldg(adj + start + j);
        uint4 r = __ldg(F + (size_t)id * 16 + sub);
        float2 f;
        f = __half22float2(*reinterpret_cast<__half2*>(&r.x)); a0 += f.x; a1 += f.y;
        f = __half22float2(*reinterpret_cast<__half2*>(&r.y)); a2 += f.x; a3 += f.y;
        f = __half22float2(*reinterpret_cast<__half2*>(&r.z)); a4 += f.x; a5 += f.y;
        f = __half22float2(*reinterpret_cast<__half2*>(&r.w)); a6 += f.x; a7 += f.y;
    }

    a0 += __shfl_down_sync(0xffffffffu, a0, 16);
    a1 += __shfl_down_sync(0xffffffffu, a1, 16);
    a2 += __shfl_down_sync(0xffffffffu, a2, 16);
    a3 += __shfl_down_sync(0xffffffffu, a3, 16);
    a4 += __shfl_down_sync(0xffffffffu, a4, 16);
    a5 += __shfl_down_sync(0xffffffffu, a5, 16);
    a6 += __shfl_down_sync(0xffffffffu, a6, 16);
    a7 += __shfl_down_sync(0xffffffffu, a7, 16);

    if (parity == 0) {
        float s = rowscale ? __ldg(rowscale + seg) : 1.0f;
        a0*=s; a1*=s; a2*=s; a3*=s; a4*=s; a5*=s; a6*=s; a7*=s;
        if (sizeof(OutT) == 2) {
            __half2 h0 = __floats2half2_rn(a0, a1);
            __half2 h1 = __floats2half2_rn(a2, a3);
            __half2 h2 = __floats2half2_rn(a4, a5);
            __half2 h3 = __floats2half2_rn(a6, a7);
            uint4 u;
            u.x = *reinterpret_cast<unsigned*>(&h0);
            u.y = *reinterpret_cast<unsigned*>(&h1);
            u.z = *reinterpret_cast<unsigned*>(&h2);
            u.w = *reinterpret_cast<unsigned*>(&h3);
            reinterpret_cast<uint4*>(reinterpret_cast<__half*>(out) + (size_t)seg * CH)[sub] = u;
        } else {
            float* p = reinterpret_cast<float*>(out) + (size_t)seg * CH + sub * 8;
            if (STREAM) {
                asm volatile("st.global.cs.v4.f32 [%0], {%1, %2, %3, %4};"
                             :: "l"(p), "f"(a0), "f"(a1), "f"(a2), "f"(a3) : "memory");
                asm volatile("st.global.cs.v4.f32 [%0], {%1, %2, %3, %4};"
                             :: "l"(p + 4), "f"(a4), "f"(a5), "f"(a6), "f"(a7) : "memory");
            } else {
                reinterpret_cast<float4*>(p)[0] = make_float4(a0, a1, a2, a3);
                reinterpret_cast<float4*>(p)[1] = make_float4(a4, a5, a6, a7);
            }
        }
    }
}

// ---------------------------------------------------------------------------
// HMMA GEMM + per-row scale, fp16 in/out, fp32 accumulate. 8 warps / block,
// 128 rows / block. A and B staged through smem with LD=136 halves (272 B =
// 17 x 16 B rows -> conflict-free ldmatrix, coalesced uint4 staging).
// Dynamic smem 69632 B; reused (LD=132 floats) for C tiles in the epilogue.
// ---------------------------------------------------------------------------
__global__ void gemm_hmma_kernel(const __half* __restrict__ A,
                                 const float*  __restrict__ Wl,
                                 const float*  __restrict__ degE,
                                 const float*  __restrict__ Wbuf,
                                 __half*       __restrict__ outh,
                                 int M) {
    extern __shared__ __align__(16) char smem[];
    __half* sA = reinterpret_cast<__half*>(smem);                      // 128 x 136
    __half* sB = reinterpret_cast<__half*>(smem) + GEMM_ROWS * SB_LD;  // 128 x 136

    const int tid  = threadIdx.x;          // 0..255
    const int warp = tid >> 5;             // 0..7
    const int lane = tid & 31;
    const int row0blk = blockIdx.x * GEMM_ROWS;

    // Stage A tile: 128 rows x 16 uint4 = 2048 uint4, 256 threads -> 8 each
    {
        const uint4* Ag = reinterpret_cast<const uint4*>(A + (size_t)row0blk * CH);
        #pragma unroll
        for (int t = 0; t < 8; t++) {
            int i = tid + t * 256;
            int r = i >> 4, c = i & 15;
            *reinterpret_cast<uint4*>(sA + r * SB_LD + c * 8) = __ldg(Ag + r * 16 + c);
        }
    }
    // Stage Wlin as fp16 (128 x 128), padded
    for (int i = tid; i < CH * CH / 2; i += 256) {
        int r = i >> 6, c = i & 63;        // 64 half2 per row
        float2 w = __ldg(reinterpret_cast<const float2*>(Wl) + i);
        reinterpret_cast<__half2*>(sB + r * SB_LD)[c] = __floats2half2_rn(w.x, w.y);
    }
    __syncthreads();

    wmma::fragment<wmma::accumulator, 16, 16, 16, float> c[8];
    #pragma unroll
    for (int nf = 0; nf < 8; nf++) wmma::fill_fragment(c[nf], 0.0f);

    const __half* Aw = sA + warp * 16 * SB_LD;
    #pragma unroll
    for (int k = 0; k < 8; k++) {
        wmma::fragment<wmma::matrix_a, 16, 16, 16, __half, wmma::row_major> af;
        wmma::load_matrix_sync(af, Aw + k * 16, SB_LD);
        #pragma unroll
        for (int nf = 0; nf < 8; nf++) {
            wmma::fragment<wmma::matrix_b, 16, 16, 16, __half, wmma::row_major> bf;
            wmma::load_matrix_sync(bf, sB + k * 16 * SB_LD + nf * 16, SB_LD);
            wmma::mma_sync(c[nf], af, bf, c[nf]);
        }
    }

    __syncthreads();   // smem reuse: fp32 C tiles, padded LD=132 (8448 B/warp)
    float* sC = reinterpret_cast<float*>(smem) + warp * 16 * SC_LD;
    #pragma unroll
    for (int nf = 0; nf < 8; nf++)
        wmma::store_matrix_sync(sC + nf * 16, c[nf], SC_LD, wmma::mem_row_major);
    __syncwarp();

    const int row0 = row0blk + warp * 16;
    const int c0 = (lane & 7) * 16;
    for (int r = lane >> 3; r < 16; r += 4) {
        int row = row0 + r;
        if (row >= M) break;
        float s = __ldg(degE + row) * __ldg(Wbuf + row);
        __half2* dst = reinterpret_cast<__half2*>(outh + (size_t)row * CH);
        #pragma unroll
        for (int cc = 0; cc < 16; cc += 2) {
            float x = sC[r * SC_LD + c0 + cc]     * s;
            float y = sC[r * SC_LD + c0 + cc + 1] * s;
            dst[(c0 + cc) >> 1] = __floats2half2_rn(x, y);
        }
    }
}

// ---------------------------------------------------------------------------
// Launch: zero+f2h(1), fill(2), gather1(3), gemm(4 <- ncu slot), gather2(5)
// ---------------------------------------------------------------------------
extern "C" void kernel_launch(void* const* d_in, const int* in_sizes, int n_in,
                              void* d_out, int out_size) {
    const float* X     = (const float*)d_in[0];
    const float* Wlin  = (const float*)d_in[1];
    const float* degE  = (const float*)d_in[2];
    const float* degV  = (const float*)d_in[3];
    const float* Wbuf  = (const float*)d_in[4];
    const int*   g1src = (const int*)d_in[5];
    const int*   g1dst = (const int*)d_in[6];
    const int    nnz   = in_sizes[5];

    float* out = (float*)d_out;

    __half *Xh, *XeSumH, *Xeh;
    int *cntE, *cntV, *adjE, *adjV;
    cudaGetSymbolAddress((void**)&Xh,     g_Xh);
    cudaGetSymbolAddress((void**)&XeSumH, g_XeSumH);
    cudaGetSymbolAddress((void**)&Xeh,    g_Xeh);
    cudaGetSymbolAddress((void**)&cntE,   g_cntE);
    cudaGetSymbolAddress((void**)&cntV,   g_cntV);
    cudaGetSymbolAddress((void**)&adjE,   g_adjE);
    cudaGetSymbolAddress((void**)&adjV,   g_adjV);

    // Idempotent, host-side only (not a stream op) — safe under graph capture.
    cudaFuncSetAttribute(gemm_hmma_kernel,
                         cudaFuncAttributeMaxDynamicSharedMemorySize, GEMM_SMEM);

    // 1) fused zero counters + X -> fp16
    {
        int n8    = N_NODES * CH / 8;
        int zeroB = (N_NODES + 255) / 256;
        int f2hB  = (n8 + 255) / 256;
        zero_f2h_kernel<<<zeroB + f2hB, 256>>>(cntV, N_NODES, cntE, N_HEDGES,
                                               zeroB, X, Xh, n8);
    }
    // 2) fixed-stride bucket fill
    fill_kernel<<<(nnz + 255) / 256, 256>>>(g1src, g1dst, cntV, cntE, adjV, adjE, nnz);
    // 3) Stage 1: node -> hyperedge gather, fp16 sums out
    {
        long long threads = (long long)N_HEDGES * 32;
        gather_sum_kernel<__half, false><<<(int)((threads + 255) / 256), 256>>>(
            Xh, adjE, cntE, STRIDE_E, STRIDE_E, nullptr, XeSumH, N_HEDGES);
    }
    // 4) HMMA projection + degE * W scaling, fp16 output table
    gemm_hmma_kernel<<<M_PAD / GEMM_ROWS, 256, GEMM_SMEM>>>(
        XeSumH, Wlin, degE, Wbuf, Xeh, N_HEDGES);
    // 5) Stage 2: hyperedge -> node gather, fused *degV, streaming fp32 out
    {
        long long threads = (long long)N_NODES * 32;
        gather_sum_kernel<float, true><<<(int)((threads + 255) / 256), 256>>>(
            Xeh, adjV, cntV, STRIDE_V, STRIDE_V, degV, out, N_NODES);
    }
}